// round 1
// baseline (speedup 1.0000x reference)
#include <cuda_runtime.h>
#include <math.h>

#define B_  8
#define S_  1024
#define D_  768
#define H_  12
#define DP_ 64

// Scratch (device globals: allocation-free per harness rules)
__device__ __align__(16) float g_qh[(size_t)B_*H_*S_*DP_];
__device__ __align__(16) float g_kh[(size_t)B_*H_*S_*DP_];
__device__ __align__(16) float g_vh[(size_t)B_*H_*S_*DP_];
__device__ __align__(16) float g_attn[(size_t)B_*S_*D_];

// ---------------------------------------------------------------------------
// C = A[M,K] @ W[N,K]^T + bias[N]
// head_split==0: out[m*N+n]   (row-major [M,N])
// head_split==1: out[((b*H+h)*S + s)*64 + d]  with m=b*S+s, n=h*64+d
// ---------------------------------------------------------------------------
__global__ __launch_bounds__(256) void gemm_nt(
    const float* __restrict__ A, const float* __restrict__ W,
    const float* __restrict__ bias, float* __restrict__ out,
    int M, int N, int K, int head_split)
{
    __shared__ float As[16][128];
    __shared__ float Bs[16][128];

    const int m0 = blockIdx.y * 128;
    const int n0 = blockIdx.x * 128;
    const int tid = threadIdx.x;
    const int ty = tid >> 4;    // 0..15
    const int tx = tid & 15;    // 0..15

    float acc[8][8];
#pragma unroll
    for (int i = 0; i < 8; i++)
#pragma unroll
        for (int j = 0; j < 8; j++) acc[i][j] = 0.f;

    for (int k0 = 0; k0 < K; k0 += 16) {
#pragma unroll
        for (int t = 0; t < 2; t++) {
            int fidx = tid + t * 256;        // 0..511
            int row  = fidx >> 2;            // 0..127
            int c4   = (fidx & 3) << 2;      // 0,4,8,12
            float4 av = *(const float4*)&A[(size_t)(m0 + row) * K + k0 + c4];
            As[c4+0][row] = av.x; As[c4+1][row] = av.y;
            As[c4+2][row] = av.z; As[c4+3][row] = av.w;
            float4 wv = *(const float4*)&W[(size_t)(n0 + row) * K + k0 + c4];
            Bs[c4+0][row] = wv.x; Bs[c4+1][row] = wv.y;
            Bs[c4+2][row] = wv.z; Bs[c4+3][row] = wv.w;
        }
        __syncthreads();

#pragma unroll
        for (int kk = 0; kk < 16; kk++) {
            float a[8], b[8];
            *(float4*)&a[0] = *(const float4*)&As[kk][8*ty];
            *(float4*)&a[4] = *(const float4*)&As[kk][8*ty+4];
            *(float4*)&b[0] = *(const float4*)&Bs[kk][8*tx];
            *(float4*)&b[4] = *(const float4*)&Bs[kk][8*tx+4];
#pragma unroll
            for (int i = 0; i < 8; i++)
#pragma unroll
                for (int j = 0; j < 8; j++)
                    acc[i][j] += a[i] * b[j];
        }
        __syncthreads();
    }

#pragma unroll
    for (int i = 0; i < 8; i++) {
        int m = m0 + 8*ty + i;
        int bb = m >> 10;          // m / S_
        int ss = m & 1023;         // m % S_
#pragma unroll
        for (int j = 0; j < 8; j++) {
            int n = n0 + 8*tx + j;
            float v = acc[i][j] + bias[n];
            if (head_split) {
                int h = n >> 6, d = n & 63;
                g_attn[0]; // no-op to keep symbol referenced pattern harmless
                out[(((size_t)bb * H_ + h) * S_ + ss) * DP_ + d] = v;
            } else {
                out[(size_t)m * N + n] = v;
            }
        }
    }
}

// ---------------------------------------------------------------------------
// Fused causal attention with relative-position (skew) bias.
// grid: (S/64, B*H), 256 threads. Online softmax, fp32.
// logits(i,j) = 0.125 * ( q_i·k_j + q_i·Er[S-1-(i-j)] ),  j <= i
// ---------------------------------------------------------------------------
__global__ __launch_bounds__(256) void attn_kernel(const float* __restrict__ Er)
{
    extern __shared__ float sm[];
    float* qs  = sm;               // [64][64]  kk-major: qs[kk*64 + row]  (pre-scaled by 0.125)
    float* ks  = qs  + 4096;       // [64][64]  kk-major
    float* ers = ks  + 4096;       // [64][128] kk-major: ers[kk*128 + e]
    float* vs  = ers + 8192;       // [64][64]  jj-major: vs[jj*64 + d]
    float* ps  = vs  + 4096;       // [64][64]  jj-major: ps[jj*64 + ii]

    const int tid = threadIdx.x;
    const int ty = tid >> 4;       // 0..15 -> S rows 4*ty..4*ty+3
    const int tx = tid & 15;       // 0..15 -> cols 4*tx..4*tx+3
    const int i0 = blockIdx.x * 64;
    const int bh = blockIdx.y;

    const float* qp = g_qh + (size_t)bh * S_ * DP_;
    const float* kp = g_kh + (size_t)bh * S_ * DP_;
    const float* vp = g_vh + (size_t)bh * S_ * DP_;

    // Load + transpose + scale Q tile (once)
    for (int idx = tid; idx < 1024; idx += 256) {
        int row = idx >> 4;
        int c4  = (idx & 15) << 2;
        float4 v = *(const float4*)&qp[(size_t)(i0 + row) * DP_ + c4];
        qs[(c4+0)*64 + row] = v.x * 0.125f;
        qs[(c4+1)*64 + row] = v.y * 0.125f;
        qs[(c4+2)*64 + row] = v.z * 0.125f;
        qs[(c4+3)*64 + row] = v.w * 0.125f;
    }

    float acc[4][4];
#pragma unroll
    for (int i = 0; i < 4; i++)
#pragma unroll
        for (int j = 0; j < 4; j++) acc[i][j] = 0.f;
    float mrow[4] = {-INFINITY, -INFINITY, -INFINITY, -INFINITY};
    float lrow[4] = {0.f, 0.f, 0.f, 0.f};

    const int ecol0 = 60 + 4*tx - 4*ty;  // 0..120, multiple of 4

    for (int j0 = 0; j0 <= i0; j0 += 64) {
        __syncthreads();   // ps/vs (prev PV) and qs (first iter) safe

        // K tile (transposed)
        for (int idx = tid; idx < 1024; idx += 256) {
            int row = idx >> 4;
            int c4  = (idx & 15) << 2;
            float4 v = *(const float4*)&kp[(size_t)(j0 + row) * DP_ + c4];
            ks[(c4+0)*64 + row] = v.x;
            ks[(c4+1)*64 + row] = v.y;
            ks[(c4+2)*64 + row] = v.z;
            ks[(c4+3)*64 + row] = v.w;
        }
        // V tile (direct)
        for (int idx = tid; idx < 1024; idx += 256) {
            int row = idx >> 4;
            int c4  = (idx & 15) << 2;
            *(float4*)&vs[row*64 + c4] = *(const float4*)&vp[(size_t)(j0 + row) * DP_ + c4];
        }
        // Er band: rows ebase .. ebase+127 (transposed; 0-fill past S)
        int ebase = S_ - 64 - i0 + j0;   // >= 0 always
        for (int idx = tid; idx < 2048; idx += 256) {
            int e  = idx >> 4;
            int c4 = (idx & 15) << 2;
            float4 v = make_float4(0.f, 0.f, 0.f, 0.f);
            if (ebase + e < S_)
                v = *(const float4*)&Er[(size_t)(ebase + e) * DP_ + c4];
            ers[(c4+0)*128 + e] = v.x;
            ers[(c4+1)*128 + e] = v.y;
            ers[(c4+2)*128 + e] = v.z;
            ers[(c4+3)*128 + e] = v.w;
        }
        __syncthreads();

        // ---- S = Qs @ (K + shifted Er)^T ----
        float sacc[4][4];
#pragma unroll
        for (int i = 0; i < 4; i++)
#pragma unroll
            for (int j = 0; j < 4; j++) sacc[i][j] = 0.f;

#pragma unroll 8
        for (int kk = 0; kk < 64; kk++) {
            float4 qf = *(const float4*)&qs[kk*64 + 4*ty];
            float4 kf = *(const float4*)&ks[kk*64 + 4*tx];
            float4 e0 = *(const float4*)&ers[kk*128 + ecol0];
            float4 e1 = *(const float4*)&ers[kk*128 + ecol0 + 4];
            float qa[4] = {qf.x, qf.y, qf.z, qf.w};
            float ka[4] = {kf.x, kf.y, kf.z, kf.w};
            float er7[7] = {e0.x, e0.y, e0.z, e0.w, e1.x, e1.y, e1.z};
#pragma unroll
            for (int ri = 0; ri < 4; ri++)
#pragma unroll
                for (int ci = 0; ci < 4; ci++)
                    sacc[ri][ci] += qa[ri] * (ka[ci] + er7[3 - ri + ci]);
        }

        // causal mask (only diagonal tile can be partially masked)
        if (j0 == i0) {
#pragma unroll
            for (int ri = 0; ri < 4; ri++)
#pragma unroll
                for (int ci = 0; ci < 4; ci++)
                    if (j0 + 4*tx + ci > i0 + 4*ty + ri) sacc[ri][ci] = -1e30f;
        }

        // online softmax per row (rows shared by 16 lanes of same ty)
#pragma unroll
        for (int ri = 0; ri < 4; ri++) {
            float mn = fmaxf(fmaxf(sacc[ri][0], sacc[ri][1]),
                             fmaxf(sacc[ri][2], sacc[ri][3]));
#pragma unroll
            for (int off = 8; off > 0; off >>= 1)
                mn = fmaxf(mn, __shfl_xor_sync(0xffffffffu, mn, off));
            float mt   = fmaxf(mrow[ri], mn);
            float corr = __expf(mrow[ri] - mt);
            mrow[ri]   = mt;
            float psum = 0.f;
#pragma unroll
            for (int ci = 0; ci < 4; ci++) {
                float p = __expf(sacc[ri][ci] - mt);
                sacc[ri][ci] = p;
                psum += p;
            }
#pragma unroll
            for (int off = 8; off > 0; off >>= 1)
                psum += __shfl_xor_sync(0xffffffffu, psum, off);
            lrow[ri] = lrow[ri] * corr + psum;
#pragma unroll
            for (int ci = 0; ci < 4; ci++) acc[ri][ci] *= corr;
        }

        // store P transposed: ps[jj][ii]
#pragma unroll
        for (int ri = 0; ri < 4; ri++)
#pragma unroll
            for (int ci = 0; ci < 4; ci++)
                ps[(4*tx + ci)*64 + (4*ty + ri)] = sacc[ri][ci];
        __syncthreads();

        // ---- O += P @ V ----
#pragma unroll 8
        for (int jj = 0; jj < 64; jj++) {
            float4 pf = *(const float4*)&ps[jj*64 + 4*ty];
            float4 vf = *(const float4*)&vs[jj*64 + 4*tx];
            float pa[4] = {pf.x, pf.y, pf.z, pf.w};
            float va[4] = {vf.x, vf.y, vf.z, vf.w};
#pragma unroll
            for (int ri = 0; ri < 4; ri++)
#pragma unroll
                for (int ci = 0; ci < 4; ci++)
                    acc[ri][ci] += pa[ri] * va[ci];
        }
    }

    // epilogue -> g_attn[B,S,D]
    const int b = bh / H_;
    const int h = bh % H_;
#pragma unroll
    for (int ri = 0; ri < 4; ri++) {
        int i = i0 + 4*ty + ri;
        float inv = 1.f / lrow[ri];
#pragma unroll
        for (int ci = 0; ci < 4; ci++) {
            g_attn[((size_t)b * S_ + i) * D_ + h * DP_ + 4*tx + ci] = acc[ri][ci] * inv;
        }
    }
}

// ---------------------------------------------------------------------------
extern "C" void kernel_launch(void* const* d_in, const int* in_sizes, int n_in,
                              void* d_out, int out_size)
{
    const float* Q  = (const float*)d_in[0];
    const float* K  = (const float*)d_in[1];
    const float* V  = (const float*)d_in[2];
    // d_in[3] = mask (causal triu, implemented analytically — unused)
    const float* Wq = (const float*)d_in[4];
    const float* bq = (const float*)d_in[5];
    const float* Wk = (const float*)d_in[6];
    const float* bk = (const float*)d_in[7];
    const float* Wv = (const float*)d_in[8];
    const float* bv = (const float*)d_in[9];
    const float* Wo = (const float*)d_in[10];
    const float* bo = (const float*)d_in[11];
    const float* Er = (const float*)d_in[12];
    float* out = (float*)d_out;

    float *qh, *kh, *vh, *attn;
    cudaGetSymbolAddress((void**)&qh,   g_qh);
    cudaGetSymbolAddress((void**)&kh,   g_kh);
    cudaGetSymbolAddress((void**)&vh,   g_vh);
    cudaGetSymbolAddress((void**)&attn, g_attn);

    const int M = B_ * S_;      // 8192
    const int N = D_;           // 768
    const int Kd = D_;          // 768
    dim3 ggrid(N / 128, M / 128);   // (6, 64)

    gemm_nt<<<ggrid, 256>>>(Q, Wq, bq, qh, M, N, Kd, 1);
    gemm_nt<<<ggrid, 256>>>(K, Wk, bk, kh, M, N, Kd, 1);
    gemm_nt<<<ggrid, 256>>>(V, Wv, bv, vh, M, N, Kd, 1);

    static_assert(S_ % 64 == 0, "");
    const int smem_bytes = 24576 * (int)sizeof(float);   // 96 KB
    cudaFuncSetAttribute(attn_kernel,
                         cudaFuncAttributeMaxDynamicSharedMemorySize, smem_bytes);
    attn_kernel<<<dim3(S_ / 64, B_ * H_), 256, smem_bytes>>>(Er);

    gemm_nt<<<ggrid, 256>>>(attn, Wo, bo, out, M, N, Kd, 0);
}

// round 3
// speedup vs baseline: 1.0371x; 1.0371x over previous
#include <cuda_runtime.h>
#include <math.h>
#include <stdint.h>

#define B_  8
#define S_  1024
#define D_  768
#define H_  12
#define DP_ 64

// Scratch (device globals: allocation-free per harness rules)
__device__ __align__(16) float g_qh[(size_t)B_*H_*S_*DP_];
__device__ __align__(16) float g_kh[(size_t)B_*H_*S_*DP_];
__device__ __align__(16) float g_vh[(size_t)B_*H_*S_*DP_];
__device__ __align__(16) float g_attn[(size_t)B_*S_*D_];

// ---------------------------------------------------------------------------
// tf32 warp MMA (legacy path: supported without the 'a' arch suffix)
// ---------------------------------------------------------------------------
__device__ __forceinline__ void mma_tf32(float c[4],
                                         uint32_t a0, uint32_t a1, uint32_t a2, uint32_t a3,
                                         uint32_t b0, uint32_t b1) {
    asm volatile(
        "mma.sync.aligned.m16n8k8.row.col.f32.tf32.tf32.f32 "
        "{%0,%1,%2,%3}, {%4,%5,%6,%7}, {%8,%9}, {%0,%1,%2,%3};"
        : "+f"(c[0]), "+f"(c[1]), "+f"(c[2]), "+f"(c[3])
        : "r"(a0), "r"(a1), "r"(a2), "r"(a3), "r"(b0), "r"(b1));
}

__device__ __forceinline__ uint32_t f2tf32(float x) {
    uint32_t y;
    asm("cvt.rna.tf32.f32 %0, %1;" : "=r"(y) : "f"(x));
    return y;
}

// ===========================================================================
// tf32 mma GEMM:  C[8192, 768] = A[8192,768] @ W[768,768]^T + bias
// Block 128x128, K-step 16, 8 warps (4x2), warp tile 32x64.
// Smem pitch 20 floats -> conflict-free fragment loads.
// head_split==1: out[((b*H+h)*S+s)*64+d]  else row-major [M,768].
// ===========================================================================
#define GK     768
#define PITCH  20

__global__ __launch_bounds__(256, 2) void gemm_tf32mma(
    const float* __restrict__ A, const float* __restrict__ W,
    const float* __restrict__ bias, float* __restrict__ out,
    int head_split)
{
    __shared__ __align__(16) uint32_t As[2][128 * PITCH];
    __shared__ __align__(16) uint32_t Bs[2][128 * PITCH];

    const int tid  = threadIdx.x;
    const int wid  = tid >> 5;
    const int lane = tid & 31;
    const int wm   = (wid >> 1) * 32;      // warp M offset (0,32,64,96)
    const int wn   = (wid & 1) * 64;       // warp N offset (0,64)
    const int m0   = blockIdx.y * 128;
    const int n0   = blockIdx.x * 128;

    const int grp  = lane >> 2;            // 0..7
    const int thr  = lane & 3;             // 0..3

    // global load coords: 2 rows per operand, 1 float4 (4 k) each
    const int lr0 = tid >> 2;              // 0..63
    const int lkg = tid & 3;               // k-group 0..3

    float c[2][8][4];
#pragma unroll
    for (int i = 0; i < 2; i++)
#pragma unroll
        for (int j = 0; j < 8; j++)
#pragma unroll
            for (int q = 0; q < 4; q++) c[i][j][q] = 0.f;

    float4 ra0, ra1, rb0, rb1;

    auto loadg = [&](int cidx) {
        const int k0 = cidx * 16;
        ra0 = *(const float4*)&A[(size_t)(m0 + lr0)      * GK + k0 + lkg * 4];
        ra1 = *(const float4*)&A[(size_t)(m0 + lr0 + 64) * GK + k0 + lkg * 4];
        rb0 = *(const float4*)&W[(size_t)(n0 + lr0)      * GK + k0 + lkg * 4];
        rb1 = *(const float4*)&W[(size_t)(n0 + lr0 + 64) * GK + k0 + lkg * 4];
    };
    auto stss = [&](int s) {
        uint4 v;
        v.x = f2tf32(ra0.x); v.y = f2tf32(ra0.y); v.z = f2tf32(ra0.z); v.w = f2tf32(ra0.w);
        *(uint4*)&As[s][lr0 * PITCH + lkg * 4] = v;
        v.x = f2tf32(ra1.x); v.y = f2tf32(ra1.y); v.z = f2tf32(ra1.z); v.w = f2tf32(ra1.w);
        *(uint4*)&As[s][(lr0 + 64) * PITCH + lkg * 4] = v;
        v.x = f2tf32(rb0.x); v.y = f2tf32(rb0.y); v.z = f2tf32(rb0.z); v.w = f2tf32(rb0.w);
        *(uint4*)&Bs[s][lr0 * PITCH + lkg * 4] = v;
        v.x = f2tf32(rb1.x); v.y = f2tf32(rb1.y); v.z = f2tf32(rb1.z); v.w = f2tf32(rb1.w);
        *(uint4*)&Bs[s][(lr0 + 64) * PITCH + lkg * 4] = v;
    };

    loadg(0);
    stss(0);
    __syncthreads();

    const int NIT = GK / 16;   // 48
    for (int cc = 0; cc < NIT; cc++) {
        const int s = cc & 1;
        if (cc < NIT - 1) loadg(cc + 1);

#pragma unroll
        for (int kb = 0; kb < 16; kb += 8) {
            uint32_t af[2][4];
#pragma unroll
            for (int i = 0; i < 2; i++) {
                int r = wm + i * 16 + grp;
                af[i][0] = As[s][r       * PITCH + kb + thr];
                af[i][1] = As[s][(r + 8) * PITCH + kb + thr];
                af[i][2] = As[s][r       * PITCH + kb + 4 + thr];
                af[i][3] = As[s][(r + 8) * PITCH + kb + 4 + thr];
            }
            uint32_t bf[8][2];
#pragma unroll
            for (int j = 0; j < 8; j++) {
                int n = wn + j * 8 + grp;
                bf[j][0] = Bs[s][n * PITCH + kb + thr];
                bf[j][1] = Bs[s][n * PITCH + kb + 4 + thr];
            }
#pragma unroll
            for (int i = 0; i < 2; i++)
#pragma unroll
                for (int j = 0; j < 8; j++)
                    mma_tf32(c[i][j], af[i][0], af[i][1], af[i][2], af[i][3],
                             bf[j][0], bf[j][1]);
        }

        if (cc < NIT - 1) {
            stss((cc + 1) & 1);
            __syncthreads();
        }
    }

    // Epilogue
#pragma unroll
    for (int i = 0; i < 2; i++) {
        int r_lo = m0 + wm + i * 16 + grp;
        int r_hi = r_lo + 8;
#pragma unroll
        for (int j = 0; j < 8; j++) {
            int n = n0 + wn + j * 8 + 2 * thr;
            float bx = bias[n], by = bias[n + 1];
            float2 v0 = make_float2(c[i][j][0] + bx, c[i][j][1] + by);
            float2 v1 = make_float2(c[i][j][2] + bx, c[i][j][3] + by);
            if (head_split) {
                int h = n >> 6, d = n & 63;
                {
                    int bb = r_lo >> 10, ss = r_lo & 1023;
                    *(float2*)&out[(((size_t)bb * H_ + h) * S_ + ss) * DP_ + d] = v0;
                }
                {
                    int bb = r_hi >> 10, ss = r_hi & 1023;
                    *(float2*)&out[(((size_t)bb * H_ + h) * S_ + ss) * DP_ + d] = v1;
                }
            } else {
                *(float2*)&out[(size_t)r_lo * D_ + n] = v0;
                *(float2*)&out[(size_t)r_hi * D_ + n] = v1;
            }
        }
    }
}

// ---------------------------------------------------------------------------
// Fused causal attention with relative-position (skew) bias. (round-1 version)
// logits(i,j) = 0.125 * ( q_i·k_j + q_i·Er[S-1-(i-j)] ),  j <= i
// ---------------------------------------------------------------------------
__global__ __launch_bounds__(256) void attn_kernel(const float* __restrict__ Er)
{
    extern __shared__ float sm[];
    float* qs  = sm;               // [64][64]  kk-major (pre-scaled by 0.125)
    float* ks  = qs  + 4096;       // [64][64]  kk-major
    float* ers = ks  + 4096;       // [64][128] kk-major
    float* vs  = ers + 8192;       // [64][64]  jj-major
    float* ps  = vs  + 4096;       // [64][64]  jj-major (P transposed)

    const int tid = threadIdx.x;
    const int ty = tid >> 4;
    const int tx = tid & 15;
    const int i0 = blockIdx.x * 64;
    const int bh = blockIdx.y;

    const float* qp = g_qh + (size_t)bh * S_ * DP_;
    const float* kp = g_kh + (size_t)bh * S_ * DP_;
    const float* vp = g_vh + (size_t)bh * S_ * DP_;

    for (int idx = tid; idx < 1024; idx += 256) {
        int row = idx >> 4;
        int c4  = (idx & 15) << 2;
        float4 v = *(const float4*)&qp[(size_t)(i0 + row) * DP_ + c4];
        qs[(c4+0)*64 + row] = v.x * 0.125f;
        qs[(c4+1)*64 + row] = v.y * 0.125f;
        qs[(c4+2)*64 + row] = v.z * 0.125f;
        qs[(c4+3)*64 + row] = v.w * 0.125f;
    }

    float acc[4][4];
#pragma unroll
    for (int i = 0; i < 4; i++)
#pragma unroll
        for (int j = 0; j < 4; j++) acc[i][j] = 0.f;
    float mrow[4] = {-INFINITY, -INFINITY, -INFINITY, -INFINITY};
    float lrow[4] = {0.f, 0.f, 0.f, 0.f};

    const int ecol0 = 60 + 4*tx - 4*ty;

    for (int j0 = 0; j0 <= i0; j0 += 64) {
        __syncthreads();

        for (int idx = tid; idx < 1024; idx += 256) {
            int row = idx >> 4;
            int c4  = (idx & 15) << 2;
            float4 v = *(const float4*)&kp[(size_t)(j0 + row) * DP_ + c4];
            ks[(c4+0)*64 + row] = v.x;
            ks[(c4+1)*64 + row] = v.y;
            ks[(c4+2)*64 + row] = v.z;
            ks[(c4+3)*64 + row] = v.w;
        }
        for (int idx = tid; idx < 1024; idx += 256) {
            int row = idx >> 4;
            int c4  = (idx & 15) << 2;
            *(float4*)&vs[row*64 + c4] = *(const float4*)&vp[(size_t)(j0 + row) * DP_ + c4];
        }
        int ebase = S_ - 64 - i0 + j0;
        for (int idx = tid; idx < 2048; idx += 256) {
            int e  = idx >> 4;
            int c4 = (idx & 15) << 2;
            float4 v = make_float4(0.f, 0.f, 0.f, 0.f);
            if (ebase + e < S_)
                v = *(const float4*)&Er[(size_t)(ebase + e) * DP_ + c4];
            ers[(c4+0)*128 + e] = v.x;
            ers[(c4+1)*128 + e] = v.y;
            ers[(c4+2)*128 + e] = v.z;
            ers[(c4+3)*128 + e] = v.w;
        }
        __syncthreads();

        float sacc[4][4];
#pragma unroll
        for (int i = 0; i < 4; i++)
#pragma unroll
            for (int j = 0; j < 4; j++) sacc[i][j] = 0.f;

#pragma unroll 8
        for (int kk = 0; kk < 64; kk++) {
            float4 qf = *(const float4*)&qs[kk*64 + 4*ty];
            float4 kf = *(const float4*)&ks[kk*64 + 4*tx];
            float4 e0 = *(const float4*)&ers[kk*128 + ecol0];
            float4 e1 = *(const float4*)&ers[kk*128 + ecol0 + 4];
            float qa[4] = {qf.x, qf.y, qf.z, qf.w};
            float ka[4] = {kf.x, kf.y, kf.z, kf.w};
            float er7[7] = {e0.x, e0.y, e0.z, e0.w, e1.x, e1.y, e1.z};
#pragma unroll
            for (int ri = 0; ri < 4; ri++)
#pragma unroll
                for (int ci = 0; ci < 4; ci++)
                    sacc[ri][ci] += qa[ri] * (ka[ci] + er7[3 - ri + ci]);
        }

        if (j0 == i0) {
#pragma unroll
            for (int ri = 0; ri < 4; ri++)
#pragma unroll
                for (int ci = 0; ci < 4; ci++)
                    if (j0 + 4*tx + ci > i0 + 4*ty + ri) sacc[ri][ci] = -1e30f;
        }

#pragma unroll
        for (int ri = 0; ri < 4; ri++) {
            float mn = fmaxf(fmaxf(sacc[ri][0], sacc[ri][1]),
                             fmaxf(sacc[ri][2], sacc[ri][3]));
#pragma unroll
            for (int off = 8; off > 0; off >>= 1)
                mn = fmaxf(mn, __shfl_xor_sync(0xffffffffu, mn, off));
            float mt   = fmaxf(mrow[ri], mn);
            float corr = __expf(mrow[ri] - mt);
            mrow[ri]   = mt;
            float psum = 0.f;
#pragma unroll
            for (int ci = 0; ci < 4; ci++) {
                float p = __expf(sacc[ri][ci] - mt);
                sacc[ri][ci] = p;
                psum += p;
            }
#pragma unroll
            for (int off = 8; off > 0; off >>= 1)
                psum += __shfl_xor_sync(0xffffffffu, psum, off);
            lrow[ri] = lrow[ri] * corr + psum;
#pragma unroll
            for (int ci = 0; ci < 4; ci++) acc[ri][ci] *= corr;
        }

#pragma unroll
        for (int ri = 0; ri < 4; ri++)
#pragma unroll
            for (int ci = 0; ci < 4; ci++)
                ps[(4*tx + ci)*64 + (4*ty + ri)] = sacc[ri][ci];
        __syncthreads();

#pragma unroll 8
        for (int jj = 0; jj < 64; jj++) {
            float4 pf = *(const float4*)&ps[jj*64 + 4*ty];
            float4 vf = *(const float4*)&vs[jj*64 + 4*tx];
            float pa[4] = {pf.x, pf.y, pf.z, pf.w};
            float va[4] = {vf.x, vf.y, vf.z, vf.w};
#pragma unroll
            for (int ri = 0; ri < 4; ri++)
#pragma unroll
                for (int ci = 0; ci < 4; ci++)
                    acc[ri][ci] += pa[ri] * va[ci];
        }
    }

    const int b = bh / H_;
    const int h = bh % H_;
#pragma unroll
    for (int ri = 0; ri < 4; ri++) {
        int i = i0 + 4*ty + ri;
        float inv = 1.f / lrow[ri];
#pragma unroll
        for (int ci = 0; ci < 4; ci++) {
            g_attn[((size_t)b * S_ + i) * D_ + h * DP_ + 4*tx + ci] = acc[ri][ci] * inv;
        }
    }
}

// ---------------------------------------------------------------------------
extern "C" void kernel_launch(void* const* d_in, const int* in_sizes, int n_in,
                              void* d_out, int out_size)
{
    const float* Q  = (const float*)d_in[0];
    const float* K  = (const float*)d_in[1];
    const float* V  = (const float*)d_in[2];
    const float* Wq = (const float*)d_in[4];
    const float* bq = (const float*)d_in[5];
    const float* Wk = (const float*)d_in[6];
    const float* bk = (const float*)d_in[7];
    const float* Wv = (const float*)d_in[8];
    const float* bv = (const float*)d_in[9];
    const float* Wo = (const float*)d_in[10];
    const float* bo = (const float*)d_in[11];
    const float* Er = (const float*)d_in[12];
    float* out = (float*)d_out;

    float *qh, *kh, *vh, *attn;
    cudaGetSymbolAddress((void**)&qh,   g_qh);
    cudaGetSymbolAddress((void**)&kh,   g_kh);
    cudaGetSymbolAddress((void**)&vh,   g_vh);
    cudaGetSymbolAddress((void**)&attn, g_attn);

    dim3 ggrid(D_ / 128, (B_ * S_) / 128);   // (6, 64)

    gemm_tf32mma<<<ggrid, 256>>>(Q, Wq, bq, qh, 1);
    gemm_tf32mma<<<ggrid, 256>>>(K, Wk, bk, kh, 1);
    gemm_tf32mma<<<ggrid, 256>>>(V, Wv, bv, vh, 1);

    const int smem_bytes = 24576 * (int)sizeof(float);   // 96 KB
    cudaFuncSetAttribute(attn_kernel,
                         cudaFuncAttributeMaxDynamicSharedMemorySize, smem_bytes);
    attn_kernel<<<dim3(S_ / 64, B_ * H_), 256, smem_bytes>>>(Er);

    gemm_tf32mma<<<ggrid, 256>>>(attn, Wo, bo, out, 0);
}